// round 4
// baseline (speedup 1.0000x reference)
#include <cuda_runtime.h>
#include <cuda_bf16.h>

// Problem shape (fixed by reference setup_inputs): B=8, N=8192, D=512.
// out[b, n]     = dot(s_bn, h_rl_bn) / (max(||s||,eps) * max(||h_rl||,eps))
// out[b, N + n] = dot(s_bn, h_fk_bn) / (max(||s||,eps) * max(||h_fk||,eps))
//
// Pure streaming workload: 402MB compulsory reads, no reuse -> bound by the
// B300 LTS throughput cap (~6300 B/cyc, path-independent). Warp-per-row with
// 12 independent LDG.128 per lane, evict-first (.cs) policy, persistent
// grid-stride launch (148 SMs x 8 CTAs) to eliminate wave-transition ramps.

#define D_DIM  512
#define N_DIM  8192          // power of two -> row/N is a shift
#define EPS    1e-12f

__global__ __launch_bounds__(256, 8)
void cosine_rows_kernel(const float* __restrict__ s,
                        const float* __restrict__ h_rl,
                        const float* __restrict__ h_fk,
                        float* __restrict__ out,
                        int n_rows)
{
    const int warps_per_block = blockDim.x >> 5;
    const int total_warps = gridDim.x * warps_per_block;
    const int warp0 = blockIdx.x * warps_per_block + (threadIdx.x >> 5);
    const int lane  = threadIdx.x & 31;

    for (int row = warp0; row < n_rows; row += total_warps) {
        const size_t base = (size_t)row * D_DIM;
        const float4* __restrict__ s4 = (const float4*)(s    + base);
        const float4* __restrict__ r4 = (const float4*)(h_rl + base);
        const float4* __restrict__ f4 = (const float4*)(h_fk + base);

        // 512 floats = 128 float4 per row; 4 float4 per lane per input.
        // All 12 loads issued up front for max MLP; streaming policy.
        float4 av[4], rv[4], fv[4];
        #pragma unroll
        for (int i = 0; i < 4; i++) av[i] = __ldcs(&s4[lane + i * 32]);
        #pragma unroll
        for (int i = 0; i < 4; i++) rv[i] = __ldcs(&r4[lane + i * 32]);
        #pragma unroll
        for (int i = 0; i < 4; i++) fv[i] = __ldcs(&f4[lane + i * 32]);

        float ss = 0.f, rr = 0.f, ff = 0.f, sr = 0.f, sf = 0.f;

        #pragma unroll
        for (int i = 0; i < 4; i++) {
            const float4 a = av[i], r = rv[i], f = fv[i];
            ss = fmaf(a.x, a.x, ss); ss = fmaf(a.y, a.y, ss);
            ss = fmaf(a.z, a.z, ss); ss = fmaf(a.w, a.w, ss);
            rr = fmaf(r.x, r.x, rr); rr = fmaf(r.y, r.y, rr);
            rr = fmaf(r.z, r.z, rr); rr = fmaf(r.w, r.w, rr);
            ff = fmaf(f.x, f.x, ff); ff = fmaf(f.y, f.y, ff);
            ff = fmaf(f.z, f.z, ff); ff = fmaf(f.w, f.w, ff);
            sr = fmaf(a.x, r.x, sr); sr = fmaf(a.y, r.y, sr);
            sr = fmaf(a.z, r.z, sr); sr = fmaf(a.w, r.w, sr);
            sf = fmaf(a.x, f.x, sf); sf = fmaf(a.y, f.y, sf);
            sf = fmaf(a.z, f.z, sf); sf = fmaf(a.w, f.w, sf);
        }

        // Warp-level butterfly reduction of all five partials.
        #pragma unroll
        for (int off = 16; off > 0; off >>= 1) {
            ss += __shfl_xor_sync(0xFFFFFFFFu, ss, off);
            rr += __shfl_xor_sync(0xFFFFFFFFu, rr, off);
            ff += __shfl_xor_sync(0xFFFFFFFFu, ff, off);
            sr += __shfl_xor_sync(0xFFFFFFFFu, sr, off);
            sf += __shfl_xor_sync(0xFFFFFFFFu, sf, off);
        }

        if (lane == 0) {
            const float ns = fmaxf(sqrtf(ss), EPS);
            const float nr = fmaxf(sqrtf(rr), EPS);
            const float nf = fmaxf(sqrtf(ff), EPS);
            const int b = row >> 13;             // row / 8192
            const int n = row & (N_DIM - 1);     // row % 8192
            float* ob = out + (size_t)b * (2 * N_DIM);
            ob[n]         = sr / (ns * nr);
            ob[N_DIM + n] = sf / (ns * nf);
        }
    }
}

extern "C" void kernel_launch(void* const* d_in, const int* in_sizes, int n_in,
                              void* d_out, int out_size)
{
    const float* s    = (const float*)d_in[0];
    const float* h_rl = (const float*)d_in[1];
    const float* h_fk = (const float*)d_in[2];
    float* out = (float*)d_out;

    const int n_rows = in_sizes[0] / D_DIM;      // B*N = 65536

    const int threads = 256;                     // 8 warps per block
    const int blocks  = 148 * 8;                 // persistent: fill all SMs at occ 8
    cosine_rows_kernel<<<blocks, threads>>>(s, h_rl, h_fk, out, n_rows);
}

// round 9
// speedup vs baseline: 1.0738x; 1.0738x over previous
#include <cuda_runtime.h>
#include <cuda_bf16.h>

// Problem shape (fixed by reference setup_inputs): B=8, N=8192, D=512.
// out[b, n]     = dot(s_bn, h_rl_bn) / (max(||s||,eps) * max(||h_rl||,eps))
// out[b, N + n] = dot(s_bn, h_fk_bn) / (max(||s||,eps) * max(||h_fk||,eps))
//
// Pure streaming workload: 402MB compulsory reads, no reuse -> bound by the
// B300 LTS throughput cap (~6300 B/cyc, path-independent). Best structure
// (measured): ONE row per warp, 12 independent LDG.128 front-batched per lane,
// evict-first (.cs) loads + streaming (.cs) stores. Inter-row parallelism
// comes from occupancy + warp retirement, NOT grid-stride loops (a loop's
// shuffle-reduction tail serializes the next row's loads -- measured 2.3us
// regression in R3).

#define D_DIM  512
#define N_DIM  8192          // power of two -> row/N is a shift
#define EPS    1e-12f

__global__ __launch_bounds__(256, 8)
void cosine_rows_kernel(const float* __restrict__ s,
                        const float* __restrict__ h_rl,
                        const float* __restrict__ h_fk,
                        float* __restrict__ out,
                        int n_rows)
{
    const int warps_per_block = blockDim.x >> 5;
    const int row  = blockIdx.x * warps_per_block + (threadIdx.x >> 5);
    const int lane = threadIdx.x & 31;
    if (row >= n_rows) return;

    const size_t base = (size_t)row * D_DIM;
    const float4* __restrict__ s4 = (const float4*)(s    + base);
    const float4* __restrict__ r4 = (const float4*)(h_rl + base);
    const float4* __restrict__ f4 = (const float4*)(h_fk + base);

    // 512 floats = 128 float4 per row; 4 float4 per lane per input.
    // All 12 loads issued up front for max MLP; streaming (evict-first) policy.
    float4 av[4], rv[4], fv[4];
    #pragma unroll
    for (int i = 0; i < 4; i++) av[i] = __ldcs(&s4[lane + i * 32]);
    #pragma unroll
    for (int i = 0; i < 4; i++) rv[i] = __ldcs(&r4[lane + i * 32]);
    #pragma unroll
    for (int i = 0; i < 4; i++) fv[i] = __ldcs(&f4[lane + i * 32]);

    float ss = 0.f, rr = 0.f, ff = 0.f, sr = 0.f, sf = 0.f;

    #pragma unroll
    for (int i = 0; i < 4; i++) {
        const float4 a = av[i], r = rv[i], f = fv[i];
        ss = fmaf(a.x, a.x, ss); ss = fmaf(a.y, a.y, ss);
        ss = fmaf(a.z, a.z, ss); ss = fmaf(a.w, a.w, ss);
        rr = fmaf(r.x, r.x, rr); rr = fmaf(r.y, r.y, rr);
        rr = fmaf(r.z, r.z, rr); rr = fmaf(r.w, r.w, rr);
        ff = fmaf(f.x, f.x, ff); ff = fmaf(f.y, f.y, ff);
        ff = fmaf(f.z, f.z, ff); ff = fmaf(f.w, f.w, ff);
        sr = fmaf(a.x, r.x, sr); sr = fmaf(a.y, r.y, sr);
        sr = fmaf(a.z, r.z, sr); sr = fmaf(a.w, r.w, sr);
        sf = fmaf(a.x, f.x, sf); sf = fmaf(a.y, f.y, sf);
        sf = fmaf(a.z, f.z, sf); sf = fmaf(a.w, f.w, sf);
    }

    // Warp-level butterfly reduction of all five partials.
    #pragma unroll
    for (int off = 16; off > 0; off >>= 1) {
        ss += __shfl_xor_sync(0xFFFFFFFFu, ss, off);
        rr += __shfl_xor_sync(0xFFFFFFFFu, rr, off);
        ff += __shfl_xor_sync(0xFFFFFFFFu, ff, off);
        sr += __shfl_xor_sync(0xFFFFFFFFu, sr, off);
        sf += __shfl_xor_sync(0xFFFFFFFFu, sf, off);
    }

    if (lane == 0) {
        const float ns = fmaxf(sqrtf(ss), EPS);
        const float nr = fmaxf(sqrtf(rr), EPS);
        const float nf = fmaxf(sqrtf(ff), EPS);
        const int b = row >> 13;             // row / 8192
        const int n = row & (N_DIM - 1);     // row % 8192
        float* ob = out + (size_t)b * (2 * N_DIM);
        __stcs(&ob[n],         sr / (ns * nr));
        __stcs(&ob[N_DIM + n], sf / (ns * nf));
    }
}

extern "C" void kernel_launch(void* const* d_in, const int* in_sizes, int n_in,
                              void* d_out, int out_size)
{
    const float* s    = (const float*)d_in[0];
    const float* h_rl = (const float*)d_in[1];
    const float* h_fk = (const float*)d_in[2];
    float* out = (float*)d_out;

    const int n_rows = in_sizes[0] / D_DIM;      // B*N = 65536

    const int threads = 256;                     // 8 warps -> 8 rows per block
    const int blocks  = (n_rows + 7) / 8;        // 8192 blocks, one row per warp
    cosine_rows_kernel<<<blocks, threads>>>(s, h_rl, h_fk, out, n_rows);
}